// round 11
// baseline (speedup 1.0000x reference)
#include <cuda_runtime.h>
#include <cuda_fp16.h>
#include <math.h>
#include <stddef.h>
#include <stdint.h>

#define B_   2
#define L_   2048
#define D_   1024
#define H_   16
#define HD   64
#define LNEG 10000.0f
#define LOG2E 1.4426950408889634f

// ---------------- device scratch ----------------
__device__ __half g_h   [8388608];                        // x | W_in | W_out (fp16)
__device__ __half g_qkvh[(size_t)3 * B_ * H_ * L_ * HD];  // q,k,v [part][b][h][l][d]
__device__ __half g_aoh [(size_t)B_ * L_ * D_];           // attn out [b][l][D]
__device__ float  g_maskf[B_ * L_];                       // LNEG*LOG2E*pad
#define XH  0
#define WIH 4194304
#define WOH 7340032

// ---------------- helpers ----------------
__device__ __forceinline__ float ex2(float x) {
    float y; asm("ex2.approx.f32 %0, %1;" : "=f"(y) : "f"(x)); return y;
}
__device__ __forceinline__ void mma_f16(float* d, const uint32_t* a,
                                        uint32_t b0, uint32_t b1, const float* c) {
    asm("mma.sync.aligned.m16n8k16.row.col.f32.f16.f16.f32 "
        "{%0,%1,%2,%3},{%4,%5,%6,%7},{%8,%9},{%10,%11,%12,%13};"
        : "=f"(d[0]), "=f"(d[1]), "=f"(d[2]), "=f"(d[3])
        : "r"(a[0]), "r"(a[1]), "r"(a[2]), "r"(a[3]),
          "r"(b0), "r"(b1),
          "f"(c[0]), "f"(c[1]), "f"(c[2]), "f"(c[3]));
}
__device__ __forceinline__ void ldsm4(uint32_t* r, uint32_t a) {
    asm volatile("ldmatrix.sync.aligned.m8n8.x4.shared.b16 {%0,%1,%2,%3}, [%4];"
        : "=r"(r[0]), "=r"(r[1]), "=r"(r[2]), "=r"(r[3]) : "r"(a));
}
__device__ __forceinline__ void ldsm4t(uint32_t* r, uint32_t a) {
    asm volatile("ldmatrix.sync.aligned.m8n8.x4.trans.shared.b16 {%0,%1,%2,%3}, [%4];"
        : "=r"(r[0]), "=r"(r[1]), "=r"(r[2]), "=r"(r[3]) : "r"(a));
}
__device__ __forceinline__ uint32_t smem_u32(const void* p) {
    uint32_t a;
    asm("{ .reg .u64 t; cvta.to.shared.u64 t, %1; cvt.u32.u64 %0, t; }" : "=r"(a) : "l"(p));
    return a;
}
__device__ __forceinline__ void cpa16(uint32_t dst_smem, const void* src) {
    asm volatile("cp.async.ca.shared.global [%0], [%1], 16;" :: "r"(dst_smem), "l"(src));
}
__device__ __forceinline__ void cpa_commit() { asm volatile("cp.async.commit_group;"); }
template<int N> __device__ __forceinline__ void cpa_wait() {
    asm volatile("cp.async.wait_group %0;" :: "n"(N));
}

// fp16 tile: rows of 128B (64 halfs), 8 chunks of 16B, chunk c of row r at c^(r&7)
#define TOFF(row, ch) (((row) << 7) + (((ch) ^ ((row) & 7)) << 4))

// ---------------- fp16 pre-conversion ----------------
__global__ void cvt_h(const float4* __restrict__ in, int off, int n4)
{
    __half2* out = (__half2*)(g_h + off);
    for (int i = blockIdx.x * blockDim.x + threadIdx.x; i < n4;
         i += gridDim.x * blockDim.x) {
        float4 v = in[i];
        out[2 * i]     = __floats2half2_rn(v.x, v.y);
        out[2 * i + 1] = __floats2half2_rn(v.z, v.w);
    }
}

// ---------------- mask dtype detection + float materialization ----------------
__global__ void mask_prep(const void* __restrict__ raw, int n)
{
    __shared__ int notint, notfloat;
    if (threadIdx.x == 0) { notint = 0; notfloat = 0; }
    __syncthreads();
    const unsigned* w = (const unsigned*)raw;
    const float*    f = (const float*)raw;
    int nw = n >> 2;
    for (int i = threadIdx.x; i < nw; i += blockDim.x) {
        unsigned x = w[i];
        if (x > 1u) notint = 1;
        float xf = f[i];
        if (xf != 0.0f && xf != 1.0f) notfloat = 1;
    }
    __syncthreads();
    const float MV = LNEG * LOG2E;
    if (!notint) {
        const int* wi = (const int*)raw;
        for (int i = threadIdx.x; i < n; i += blockDim.x)
            g_maskf[i] = wi[i] ? MV : 0.0f;
    } else if (!notfloat) {
        for (int i = threadIdx.x; i < n; i += blockDim.x)
            g_maskf[i] = (f[i] != 0.0f) ? MV : 0.0f;
    } else {
        const unsigned char* c = (const unsigned char*)raw;
        for (int i = threadIdx.x; i < n; i += blockDim.x)
            g_maskf[i] = c[i] ? MV : 0.0f;
    }
}

// ---------------- fp16 NT GEMM: 128x128 tile, k-slab 64, 3-stage cp.async -----------
// MODE 1: A = x (g_h+XH), B = W_in (g_h+WIH) -> scatter q/k/v fp16 [part][b][h][l][d]
// MODE 0: A = g_aoh,      B = W_out (g_h+WOH) -> C row-major fp32 (+bias)
#define STG 3
template<int MODE>
__global__ __launch_bounds__(256, 2) void hgemm(
    const float* __restrict__ bias, float* __restrict__ C, int N)
{
    extern __shared__ char smem[];
    const uint32_t sb = smem_u32(smem);

    const int tid = threadIdx.x;
    const int lane = tid & 31, wid = tid >> 5;
    const int gid = lane >> 2, tig = lane & 3;
    const int sub = lane >> 3, lr = lane & 7;
    const int subhi = sub >> 1, sublo = sub & 1;
    const int wm = wid & 1, wn = wid >> 1;
    const int m0 = blockIdx.y * 128, n0 = blockIdx.x * 128;

    const __half* Ap = (MODE == 0) ? g_aoh : (g_h + XH);
    const __half* Bw = (MODE == 0) ? (g_h + WOH) : (g_h + WIH);
    const int K = D_;

    float acc[4][4][4];
    #pragma unroll
    for (int mt = 0; mt < 4; mt++)
        #pragma unroll
        for (int nt = 0; nt < 4; nt++)
            #pragma unroll
            for (int c = 0; c < 4; c++) acc[mt][nt][c] = 0.0f;

    auto stage = [&](int t, int s) {
        uint32_t base = sb + s * 32768;
        #pragma unroll
        for (int p = 0; p < 8; p++) {
            int idx = tid + 256 * p;
            int mat = idx >> 10;
            int rc  = idx & 1023;
            int row = rc >> 3, ch = rc & 7;
            const __half* src = (mat ? Bw + (size_t)(n0 + row) * K
                                     : Ap + (size_t)(m0 + row) * K) + t * 64 + ch * 8;
            cpa16(base + mat * 16384 + TOFF(row, ch), src);
        }
        cpa_commit();
    };

    stage(0, 0);
    stage(1, 1);
    stage(2, 2);

    const int T = K / 64;
    for (int t = 0; t < T; t++) {
        cpa_wait<STG - 1>();
        __syncthreads();
        uint32_t Ab = sb + (t % STG) * 32768;
        uint32_t Bb = Ab + 16384;

        #pragma unroll
        for (int kk = 0; kk < 4; kk++) {
            int ch = 2 * kk + subhi;
            uint32_t afr[4][4], bfr[2][4];
            #pragma unroll
            for (int mt = 0; mt < 4; mt++) {
                int row = wm * 64 + mt * 16 + sublo * 8 + lr;
                ldsm4(afr[mt], Ab + ((row << 7) + ((ch ^ lr) << 4)));
            }
            #pragma unroll
            for (int ng = 0; ng < 2; ng++) {
                int row = wn * 32 + ng * 16 + sublo * 8 + lr;
                ldsm4(bfr[ng], Bb + ((row << 7) + ((ch ^ lr) << 4)));
            }
            #pragma unroll
            for (int mt = 0; mt < 4; mt++)
                #pragma unroll
                for (int nt = 0; nt < 4; nt++)
                    mma_f16(acc[mt][nt], afr[mt],
                            bfr[nt >> 1][nt & 1], bfr[nt >> 1][(nt & 1) + 2],
                            acc[mt][nt]);
        }
        __syncthreads();
        if (t + STG < T) stage(t + STG, (t + STG) % STG);
    }

    #pragma unroll
    for (int mt = 0; mt < 4; mt++) {
        #pragma unroll
        for (int hh = 0; hh < 2; hh++) {
            int m = m0 + wm * 64 + mt * 16 + gid + hh * 8;
            #pragma unroll
            for (int nt = 0; nt < 4; nt++) {
                int n = n0 + wn * 32 + nt * 8 + 2 * tig;
                float vx = acc[mt][nt][2 * hh]     + bias[n];
                float vy = acc[mt][nt][2 * hh + 1] + bias[n + 1];
                if (MODE == 0) {
                    float2 val = { vx, vy };
                    *(float2*)&C[(size_t)m * N + n] = val;
                } else {
                    int part = n >> 10;
                    int col  = n & 1023;
                    int hd   = col >> 6;
                    int dd   = col & 63;
                    int bb   = m >> 11;
                    int ll   = m & 2047;
                    *(__half2*)&g_qkvh[((((size_t)part * B_ + bb) * H_ + hd) * L_ + ll) * HD + dd] =
                        __floats2half2_rn(vx, vy);
                }
            }
        }
    }
}

// ---------------- flash attention: q-tile 128, double-buffered K/V, reg bias ---------
// 256 threads = 8 warps; warp w owns q rows [w*16, w*16+16) of a 128-row q block.
// smem: buf0 K 8KB | buf0 V 8KB | buf1 K 8KB | buf1 V 8KB | Q/P 16KB  = 48 KB
__global__ __launch_bounds__(256, 2) void flash_h(const float* __restrict__ attn_bias)
{
    extern __shared__ char smf[];
    const uint32_t sb = smem_u32(smf);      // K/V double buffer: s*16384 (K +0, V +8192)
    const uint32_t sP = sb + 32768;         // Q then P: 128 rows x 128B

    const int tid = threadIdx.x;
    const int lane = tid & 31, w = tid >> 5;
    const int gid = lane >> 2, tig = lane & 3;
    const int sub = lane >> 3, lr = lane & 7;
    const int subhi = sub >> 1, sublo = sub & 1;
    const int b = blockIdx.z, h = blockIdx.y, q0 = blockIdx.x * 128;

    const __half* Qg = g_qkvh + (((size_t)(0 * B_ + b) * H_ + h) * L_ + q0) * HD;
    const __half* Kg = g_qkvh + (((size_t)(1 * B_ + b) * H_ + h) * L_) * HD;
    const __half* Vg = g_qkvh + (((size_t)(2 * B_ + b) * H_ + h) * L_) * HD;
    const float* biasbase = attn_bias + (((size_t)b * H_ + h) * L_ + q0) * L_;
    const float* mkb = g_maskf + b * L_;

    // stage Q (128 rows x 8 chunks = 1024 cp.async over 256 threads)
    #pragma unroll
    for (int p = 0; p < 4; p++) {
        int idx = tid + 256 * p;
        int row = idx >> 3, ch = idx & 7;
        cpa16(sP + TOFF(row, ch), Qg + row * HD + ch * 8);
    }
    cpa_commit(); cpa_wait<0>();
    __syncthreads();

    uint32_t aq[4][4];
    {
        int row = w * 16 + sublo * 8 + lr;
        #pragma unroll
        for (int kk = 0; kk < 4; kk++)
            ldsm4(aq[kk], sP + ((row << 7) + (((2 * kk + subhi) ^ lr) << 4)));
    }

    float o[8][4];
    #pragma unroll
    for (int nt = 0; nt < 8; nt++)
        #pragma unroll
        for (int c = 0; c < 4; c++) o[nt][c] = 0.0f;
    float den[2] = { 0.0f, 0.0f };

    const float SC = 0.125f * LOG2E;

    // K/V tile stager: 2 mats x 64 rows x 8 chunks = 1024 cp.async over 256 threads
    auto stage = [&](int t, int s) {
        uint32_t base = sb + s * 16384;
        #pragma unroll
        for (int p = 0; p < 4; p++) {
            int idx = tid + 256 * p;
            int mat = idx >> 9;
            int rc  = idx & 511;
            int row = rc >> 3, ch = rc & 7;
            const __half* src = (mat ? Vg : Kg) + (size_t)(t * 64 + row) * HD + ch * 8;
            cpa16(base + mat * 8192 + TOFF(row, ch), src);
        }
        cpa_commit();
    };

    stage(0, 0);

    const int T = L_ / 64;   // 32 key tiles
    for (int t = 0; t < T; t++) {
        const int k0 = t * 64;
        __syncthreads();               // all warps done reading buf (t+1)&1 (tile t-1)
        if (t + 1 < T) stage(t + 1, (t + 1) & 1);

        // bias+mask -> registers in fragment layout (overlaps staging & upcoming mma)
        float2 comb[2][8];
        #pragma unroll
        for (int nt = 0; nt < 8; nt++) {
            float2 mk = *(const float2*)(mkb + k0 + nt * 8 + 2 * tig);
            #pragma unroll
            for (int hh = 0; hh < 2; hh++) {
                int r = w * 16 + gid + 8 * hh;
                float2 bb = *(const float2*)(biasbase + (size_t)r * L_ + k0 + nt * 8 + 2 * tig);
                comb[hh][nt].x = fmaf(bb.x, LOG2E, -mk.x);
                comb[hh][nt].y = fmaf(bb.y, LOG2E, -mk.y);
            }
        }

        if (t + 1 < T) cpa_wait<1>(); else cpa_wait<0>();
        __syncthreads();               // K/V tile t visible
        const uint32_t sK = sb + (t & 1) * 16384;
        const uint32_t sV = sK + 8192;

        // S = Q K^T
        float s[8][4];
        #pragma unroll
        for (int nt = 0; nt < 8; nt++)
            #pragma unroll
            for (int c = 0; c < 4; c++) s[nt][c] = 0.0f;
        #pragma unroll
        for (int kk = 0; kk < 4; kk++) {
            int ch = 2 * kk + subhi;
            uint32_t bfr[4][4];
            #pragma unroll
            for (int ng = 0; ng < 4; ng++) {
                int row = ng * 16 + sublo * 8 + lr;
                ldsm4(bfr[ng], sK + ((row << 7) + ((ch ^ lr) << 4)));
            }
            #pragma unroll
            for (int nt = 0; nt < 8; nt++)
                mma_f16(s[nt], aq[kk],
                        bfr[nt >> 1][nt & 1], bfr[nt >> 1][(nt & 1) + 2],
                        s[nt]);
        }

        // softmax (base 2, no max subtraction); write P fp16 into sP
        #pragma unroll
        for (int hh = 0; hh < 2; hh++) {
            int r = w * 16 + gid + 8 * hh;
            float ls = 0.0f;
            #pragma unroll
            for (int nt = 0; nt < 8; nt++) {
                float p0 = ex2(fmaf(s[nt][2 * hh],     SC, comb[hh][nt].x));
                float p1 = ex2(fmaf(s[nt][2 * hh + 1], SC, comb[hh][nt].y));
                ls += p0 + p1;
                *(__half2*)(smf + 32768 + ((r << 7) + ((nt ^ (r & 7)) << 4) + 4 * tig)) =
                    __floats2half2_rn(p0, p1);
            }
            den[hh] += ls;
        }
        __syncwarp();   // P rows are warp-private

        // O += P V  (trans ldmatrix of V [key][d]; k-pair (r0,r1)/(r2,r3))
        #pragma unroll
        for (int kk = 0; kk < 4; kk++) {
            uint32_t pa[4];
            {
                int row = w * 16 + sublo * 8 + lr;
                ldsm4(pa, sP + ((row << 7) + (((2 * kk + subhi) ^ lr) << 4)));
            }
            uint32_t vf[4][4];
            #pragma unroll
            for (int ng = 0; ng < 4; ng++) {
                int row = kk * 16 + sublo * 8 + lr;
                int ch  = 2 * ng + subhi;
                ldsm4t(vf[ng], sV + ((row << 7) + ((ch ^ lr) << 4)));
            }
            #pragma unroll
            for (int nt = 0; nt < 8; nt++)
                mma_f16(o[nt], pa,
                        vf[nt >> 1][(nt & 1) * 2], vf[nt >> 1][(nt & 1) * 2 + 1],
                        o[nt]);
        }
    }

    // reduce den within lane-quad
    #pragma unroll
    for (int hh = 0; hh < 2; hh++) {
        den[hh] += __shfl_xor_sync(0xffffffffu, den[hh], 1);
        den[hh] += __shfl_xor_sync(0xffffffffu, den[hh], 2);
    }

    // normalize + write fp16 attn-out (feeds MODE0 GEMM)
    #pragma unroll
    for (int hh = 0; hh < 2; hh++) {
        float inv = 1.0f / den[hh];
        int l = q0 + w * 16 + gid + 8 * hh;
        #pragma unroll
        for (int nt = 0; nt < 8; nt++) {
            *(__half2*)&g_aoh[((size_t)b * L_ + l) * D_ + h * HD + nt * 8 + 2 * tig] =
                __floats2half2_rn(o[nt][2 * hh] * inv, o[nt][2 * hh + 1] * inv);
        }
    }
}

// ---------------- launch ----------------
extern "C" void kernel_launch(void* const* d_in, const int* in_sizes, int n_in,
                              void* d_out, int out_size)
{
    const float* x      = (const float*)d_in[0];
    const void*  mask   = d_in[1];
    const float* attn_b = (const float*)d_in[2];
    const float* b_in   = (const float*)d_in[4];
    const float* b_out  = (const float*)d_in[6];
    float*       out    = (float*)d_out;

    (void)in_sizes; (void)n_in; (void)out_size;

    mask_prep<<<1, 256>>>(mask, B_ * L_);
    cvt_h<<<1024, 256>>>((const float4*)x,       XH,  (B_ * L_ * D_) / 4);
    cvt_h<<<1024, 256>>>((const float4*)d_in[3], WIH, (3 * D_ * D_) / 4);
    cvt_h<<<512,  256>>>((const float4*)d_in[5], WOH, (D_ * D_) / 4);

    int gsmem = STG * 32768;   // 98,304 B
    cudaFuncSetAttribute(hgemm<1>, cudaFuncAttributeMaxDynamicSharedMemorySize, gsmem);
    cudaFuncSetAttribute(hgemm<0>, cudaFuncAttributeMaxDynamicSharedMemorySize, gsmem);

    // QKV projection -> q/k/v fp16
    hgemm<1><<<dim3((3 * D_) / 128, (B_ * L_) / 128), 256, gsmem>>>(
        b_in, nullptr, 3 * D_);

    int fsmem = 49152;
    cudaFuncSetAttribute(flash_h, cudaFuncAttributeMaxDynamicSharedMemorySize, fsmem);
    flash_h<<<dim3(L_ / 128, H_, B_), 256, fsmem>>>(attn_b);

    // Output projection -> fp32 out
    hgemm<0><<<dim3(D_ / 128, (B_ * L_) / 128), 256, gsmem>>>(
        b_out, out, D_);
}